// round 9
// baseline (speedup 1.0000x reference)
#include <cuda_runtime.h>
#include <cuda_bf16.h>
#include <stdint.h>

// Shapes (fixed):
//   updates: (8,128,128,256) float32 -> 33,554,432 elems
//   mask:    same shape int32 in [0, 16,777,216)
//   output:  (8,256,256,256) float32 -> 134,217,728 elems (512 MB)
// out[mask[i] + (i>>22)<<22] += updates[i]; rest zeros.
//
// LTS-byte-minimal design: 4 batch-pair passes, each input read ONCE.
//   pass p covers batches {2p, 2p+1}; atomic window = [2p*C, (2p+5)*C), C=4.19M
//   (84 MB, fits L2; consecutive windows share 50 MB resident lines).
//   pass p also zero-fills pass p+1's NEW window slice [(2p+5)C,(2p+7)C)
//   with plain stores (1 float4/thread) -> slice is L2-dirty for pass p+1.
// Upfront: memset pass-0 window [0, 5C). Side stream: memset dead region
// [46,137,344, end) (incl. tail; never an atomic target).

#define CHUNK        4194304u                   // 4C = one batch offset unit
#define BATCH_V4     (CHUNK / 4u)               // 1,048,576
#define PASS_V4      (2u * BATCH_V4)            // 2,097,152 threads per pass
#define BATCH_V4_SH  20
#define BATCH_OFF_SH 22
#define SCATTER_END  46137344u                  // 11 chunks
#define OUT_ELEMS    134217728u

__global__ __launch_bounds__(256, 8)
void scatter_pair_kernel(const float4* __restrict__ upd4,
                         const int4*  __restrict__ msk4,
                         float* __restrict__ out,
                         unsigned int p)         // pass index 0..3
{
    unsigned int i = blockIdx.x * 256u + threadIdx.x;   // [0, PASS_V4)
    unsigned int g = p * PASS_V4 + i;                   // global v4 index

    float4 u = __ldcs(upd4 + g);
    int4   m = __ldcs(msk4 + g);

    // Zero the NEXT pass's new window slice: [(2p+5)*CHUNK, (2p+7)*CHUNK).
    // 2 chunks = 2,097,152 float4 == exactly one store per thread.
    // Plain store -> stays dirty in L2 for pass p+1's atomics.
    if (p < 3u) {
        float4* out4 = (float4*)out;
        unsigned int slice_v4 = (2u * p + 5u) * (CHUNK / 4u);
        out4[slice_v4 + i] = make_float4(0.f, 0.f, 0.f, 0.f);
    }

    // Unconditional scatter-add: all targets lie in this pass's window.
    unsigned int base = (g >> BATCH_V4_SH) << BATCH_OFF_SH;
    atomicAdd(out + base + (unsigned int)m.x, u.x);
    atomicAdd(out + base + (unsigned int)m.y, u.y);
    atomicAdd(out + base + (unsigned int)m.z, u.z);
    atomicAdd(out + base + (unsigned int)m.w, u.w);
}

extern "C" void kernel_launch(void* const* d_in, const int* in_sizes, int n_in,
                              void* d_out, int out_size)
{
    const float4* upd4 = (const float4*)d_in[0];
    const int4*   msk4 = (const int4*)d_in[1];
    float* out = (float*)d_out;

    static cudaStream_t side = nullptr;
    static cudaEvent_t ev_fork = nullptr, ev_tail = nullptr;
    if (side == nullptr) {
        cudaStreamCreateWithFlags(&side, cudaStreamNonBlocking);
        cudaEventCreateWithFlags(&ev_fork, cudaEventDisableTiming);
        cudaEventCreateWithFlags(&ev_tail, cudaEventDisableTiming);
    }

    const int threads = 256;
    const int blocks  = (int)(PASS_V4 / threads);   // 8192

    // Side stream: zero the never-scattered region [SCATTER_END, OUT_ELEMS).
    cudaEventRecord(ev_fork, 0);
    cudaStreamWaitEvent(side, ev_fork, 0);
    cudaMemsetAsync(out + SCATTER_END, 0,
                    (size_t)(OUT_ELEMS - SCATTER_END) * sizeof(float), side);
    cudaEventRecord(ev_tail, side);

    // Zero pass-0's window [0, 5*CHUNK) = 84 MB.
    cudaMemsetAsync(out, 0, (size_t)(5u * CHUNK) * sizeof(float), 0);

    // Four batch-pair passes; each zeroes the next pass's new slice.
    for (unsigned int p = 0; p < 4; p++)
        scatter_pair_kernel<<<blocks, threads>>>(upd4, msk4, out, p);

    cudaStreamWaitEvent(0, ev_tail, 0);
}